// round 13
// baseline (speedup 1.0000x reference)
#include <cuda_runtime.h>

#define NU 100000
#define NI 50000
#define NN 150000
#define HD 64
#define NE 1200000
#define CHUNK 1024
#define NCHUNK 147   // ceil(NN / CHUNK)

typedef unsigned long long ull;

// Scratch (static device globals; zero-initialized at load).
// bufA/bufB/v1 have a zero row/slot at index NN (never written): padding target.
__device__ __align__(16) float g_bufA[(NN + 1) * HD];
__device__ __align__(16) float g_bufB[(NN + 1) * HD];
__device__ float g_u1[NN];
__device__ float g_v1[NN + 1];
__device__ float g_u2[NN];
__device__ float g_dinv[NN];
__device__ __align__(16) int g_cnt[NN];
__device__ int   g_flag[NCHUNK];
__device__ int   g_off[NN + 1];
__device__ int   g_cur[NN];
__device__ int   g_edge[NE];
__device__ float g_W123[HD * HD];
__device__ float g_T[HD * HD];
__device__ float g_bv1[HD];
__device__ float g_bv2[HD];
__device__ unsigned g_barcnt;
__device__ volatile unsigned g_bargen;

#define FMA2(acc, a, b) \
    asm("fma.rn.f32x2 %0, %1, %2, %0;" : "+l"(acc) : "l"(a), "l"(b))
#define MUL2(d, a, b) \
    asm("mul.rn.f32x2 %0, %1, %2;" : "=l"(d) : "l"(a), "l"(b))
#define ADD2(acc, b) \
    asm("add.rn.f32x2 %0, %0, %1;" : "+l"(acc) : "l"(b))
#define DUPF(d, f) \
    asm("mov.b64 %0, {%1, %1};" : "=l"(d) : "f"(f))

// Generation-counter grid barrier. Safe iff all nblk blocks co-resident
// (guaranteed by occupancy-based grid sizing at launch).
__device__ __forceinline__ void grid_bar(int nblk) {
    __threadfence();
    __syncthreads();
    if (threadIdx.x == 0) {
        unsigned gen = g_bargen;
        if (atomicAdd(&g_barcnt, 1u) == (unsigned)(nblk - 1)) {
            g_barcnt = 0u;
            __threadfence();
            g_bargen = gen + 1u;
        } else {
            while (g_bargen == gen) __nanosleep(128);
        }
        __threadfence();
    }
    __syncthreads();
}

// ---------------------------------------------------------------------------
__global__ void __launch_bounds__(256, 8)
k_all(int nblk, const int* __restrict__ ei,
      const float* __restrict__ ue, const float* __restrict__ ie,
      const float* __restrict__ Wsrc, const float* __restrict__ bs,
      float* __restrict__ out)
{
    __shared__ float sW[64 * 64];    // 16 KB
    __shared__ float sX[32 * 68];    // 8.7 KB
    __shared__ int   sI[40];
    int tid  = threadIdx.x;
    int bid  = blockIdx.x;
    int nthr = nblk * 256;
    unsigned gmask = 0xFFu << (tid & 24);

    // ================= phase 1: deg (blocks 0..nblk-2) | wprod (last) =====
    if (bid == nblk - 1) {
        // T = W2@W3 ; W123 = W1@T ; bv2 = b1@T ; bv1 = b2@W3
        for (int i = tid; i < 4096; i += 256) sW[i] = Wsrc[4096 + i];   // W2
        __syncthreads();
        for (int i = tid; i < 4096; i += 256) {
            int r = i >> 6, c = i & 63;
            float s = 0.f;
            #pragma unroll
            for (int k = 0; k < 64; k++) s += sW[r * 64 + k] * Wsrc[8192 + k * 64 + c];
            g_T[i] = s;
        }
        __syncthreads();
        for (int i = tid; i < 4096; i += 256) sW[i] = Wsrc[i];          // W1
        __syncthreads();
        for (int i = tid; i < 4096; i += 256) {
            int r = i >> 6, c = i & 63;
            float s = 0.f;
            #pragma unroll
            for (int k = 0; k < 64; k++) s += sW[r * 64 + k] * g_T[k * 64 + c];
            g_W123[i] = s;
        }
        if (tid < 64) {
            float s = 0.f, s2 = 0.f;
            #pragma unroll
            for (int k = 0; k < 64; k++) {
                s  += bs[k]      * g_T[k * 64 + tid];
                s2 += bs[64 + k] * Wsrc[8192 + k * 64 + tid];
            }
            g_bv2[tid] = s;
            g_bv1[tid] = s2;
        }
    } else {
        int stride = (nblk - 1) * 256;
        for (int e = bid * 256 + tid; e < NE; e += stride)
            atomicAdd(&g_cnt[ei[NE + e]], 1);
    }
    grid_bar(nblk);

    // ================= phase 2: scan (chunked, decoupled lookback) =========
    for (int ch = bid; ch < NCHUNK; ch += nblk) {
        int base0 = ch * CHUNK + tid * 4;
        int4 cv = make_int4(0, 0, 0, 0);
        if (base0 < NN) cv = *(const int4*)&g_cnt[base0];
        int s1 = cv.x, s2v = s1 + cv.y, s3 = s2v + cv.z, s4 = s3 + cv.w;
        int lane = tid & 31, wid = tid >> 5;
        int x = s4;
        #pragma unroll
        for (int o = 1; o < 32; o <<= 1) {
            int y = __shfl_up_sync(0xffffffffu, x, o);
            if (lane >= o) x += y;
        }
        if (lane == 31) sI[wid] = x;
        if (tid == 0) sI[32] = 0;
        __syncthreads();
        if (tid < 8) {
            int v = sI[tid];
            #pragma unroll
            for (int o = 1; o < 8; o <<= 1) {
                int y = __shfl_up_sync(0xFFu, v, o);
                if (tid >= o) v += y;
            }
            sI[tid] = v;
        }
        __syncthreads();
        int total = sI[7];
        if (tid == 0) *((volatile int*)&g_flag[ch]) = total + 1;   // publish
        int thr_excl = (wid ? sI[wid - 1] : 0) + x - s4;
        for (int p = tid; p < ch; p += 256) {                      // lookback
            int v;
            do { v = *((volatile int*)&g_flag[p]); } while (v == 0);
            atomicAdd(&sI[32], v - 1);
        }
        __syncthreads();
        int gb = sI[32] + thr_excl;
        if (base0 < NN) {
            g_off[base0 + 1] = gb + s1;
            g_off[base0 + 2] = gb + s2v;
            g_off[base0 + 3] = gb + s3;
            g_off[base0 + 4] = gb + s4;
            g_cur[base0]     = gb;
            g_cur[base0 + 1] = gb + s1;
            g_cur[base0 + 2] = gb + s2v;
            g_cur[base0 + 3] = gb + s3;
            g_dinv[base0]     = rsqrtf((float)(cv.x + 1));
            g_dinv[base0 + 1] = rsqrtf((float)(cv.y + 1));
            g_dinv[base0 + 2] = rsqrtf((float)(cv.z + 1));
            g_dinv[base0 + 3] = rsqrtf((float)(cv.w + 1));
            if (base0 == 0) g_off[0] = 0;
        }
        __syncthreads();
    }
    grid_bar(nblk);

    // ================= phase 3: bucket fill ================================
    for (int e = bid * 256 + tid; e < NE; e += nthr) {
        int s = ei[e];
        int d = ei[NE + e];
        int pos = atomicAdd(&g_cur[d], 1);
        g_edge[pos] = s;
    }
    grid_bar(nblk);

    // ================= phase 4: agg1 =======================================
    // z1[d] = dinv_d^2 (sum dinv_s x0[s] + dinv_d x0[d]); u1, v1 alongside.
    for (int slot = bid * 256 + tid; slot < NN * 8; slot += nthr) {
        int node = slot >> 3;
        int c = slot & 7;
        int beg = g_off[node];
        int end = g_off[node + 1];
        float dv = rsqrtf((float)(end - beg + 1));
        ull pdv; DUPF(pdv, dv);

        const float* selfp = (node < NU) ? ue + (size_t)node * 64
                                         : ie + (size_t)(node - NU) * 64;
        ulonglong2 s0 = *(const ulonglong2*)(selfp + c * 4);
        ulonglong2 s1 = *(const ulonglong2*)(selfp + 32 + c * 4);
        ull a0, a1, a2, a3;
        MUL2(a0, s0.x, pdv); MUL2(a1, s0.y, pdv);
        MUL2(a2, s1.x, pdv); MUL2(a3, s1.y, pdv);
        float uacc = 0.0f;

        int idx = beg + c;
        int   ed = (idx < end) ? g_edge[idx] : 0;
        float wv = (idx < end) ? g_dinv[ed] : 0.0f;
        for (int j0 = beg; j0 < end; j0 += 8) {
            int nidx = j0 + 8 + c;
            int   edn = (nidx < end) ? g_edge[nidx] : 0;
            float wn  = (nidx < end) ? g_dinv[edn] : 0.0f;
            uacc += wv;
            #pragma unroll
            for (int k = 0; k < 8; k++) {
                int   s = __shfl_sync(gmask, ed, k, 8);
                float w = __shfl_sync(gmask, wv, k, 8);
                ull ww; DUPF(ww, w);
                const float* hp = (s < NU) ? ue + (size_t)s * 64
                                           : ie + (size_t)(s - NU) * 64;
                ulonglong2 h0 = *(const ulonglong2*)(hp + c * 4);
                ulonglong2 h1 = *(const ulonglong2*)(hp + 32 + c * 4);
                FMA2(a0, ww, h0.x); FMA2(a1, ww, h0.y);
                FMA2(a2, ww, h1.x); FMA2(a3, ww, h1.y);
            }
            ed = edn; wv = wn;
        }

        float dv2 = dv * dv;
        ull pdv2; DUPF(pdv2, dv2);
        MUL2(a0, a0, pdv2); MUL2(a1, a1, pdv2);
        MUL2(a2, a2, pdv2); MUL2(a3, a3, pdv2);
        *(ulonglong2*)(g_bufA + (size_t)node * 64 + c * 4)      = make_ulonglong2(a0, a1);
        *(ulonglong2*)(g_bufA + (size_t)node * 64 + 32 + c * 4) = make_ulonglong2(a2, a3);

        #pragma unroll
        for (int o = 4; o > 0; o >>= 1)
            uacc += __shfl_down_sync(gmask, uacc, o, 8);
        if (c == 0) {
            float u1 = dv * (uacc + dv);
            g_u1[node] = u1;
            g_v1[node] = dv * u1;
        }
    }
    grid_bar(nblk);

    // ================= phase 5: agg2 =======================================
    for (int slot = bid * 256 + tid; slot < NN * 8; slot += nthr) {
        int node = slot >> 3;
        int c = slot & 7;
        int beg = g_off[node];
        int end = g_off[node + 1];
        float dv = rsqrtf((float)(end - beg + 1));

        const float* selfp = g_bufA + (size_t)node * 64;
        ulonglong2 s0 = *(const ulonglong2*)(selfp + c * 4);
        ulonglong2 s1 = *(const ulonglong2*)(selfp + 32 + c * 4);
        ull a0 = s0.x, a1 = s0.y, a2 = s1.x, a3 = s1.y;
        float uacc = 0.0f;

        int idx = beg + c;
        int ed = (idx < end) ? g_edge[idx] : NN;
        for (int j0 = beg; j0 < end; j0 += 8) {
            int nidx = j0 + 8 + c;
            int edn = (nidx < end) ? g_edge[nidx] : NN;
            uacc += g_v1[ed];                     // v1[NN] == 0
            #pragma unroll
            for (int k = 0; k < 8; k++) {
                int s = __shfl_sync(gmask, ed, k, 8);
                const float* hp = g_bufA + (size_t)s * 64;
                ulonglong2 h0 = *(const ulonglong2*)(hp + c * 4);
                ulonglong2 h1 = *(const ulonglong2*)(hp + 32 + c * 4);
                ADD2(a0, h0.x); ADD2(a1, h0.y);
                ADD2(a2, h1.x); ADD2(a3, h1.y);
            }
            ed = edn;
        }

        float dv2 = dv * dv;
        ull pdv2; DUPF(pdv2, dv2);
        MUL2(a0, a0, pdv2); MUL2(a1, a1, pdv2);
        MUL2(a2, a2, pdv2); MUL2(a3, a3, pdv2);
        *(ulonglong2*)(g_bufB + (size_t)node * 64 + c * 4)      = make_ulonglong2(a0, a1);
        *(ulonglong2*)(g_bufB + (size_t)node * 64 + 32 + c * 4) = make_ulonglong2(a2, a3);

        #pragma unroll
        for (int o = 4; o > 0; o >>= 1)
            uacc += __shfl_down_sync(gmask, uacc, o, 8);
        if (c == 0) g_u2[node] = dv * (uacc + g_v1[node]);
    }
    grid_bar(nblk);

    // ================= phase 6: agg3 + GEMM + embcopy + state re-zero ======
    for (int i = tid; i < 1024; i += 256)
        ((float4*)sW)[i] = ((const float4*)g_W123)[i];
    if (bid == 0 && tid < NCHUNK) g_flag[tid] = 0;
    const float* b3 = bs + 128;
    int r = tid >> 3;
    int c = tid & 7;
    int cb = c << 3;

    for (int t = bid; t < (NN + 31) / 32; t += nblk) {
        __syncthreads();                    // sW ready / sX reuse safe
        int node = t * 32 + r;
        if (node < NN) {
            int beg = g_off[node];
            int end = g_off[node + 1];
            float dv = rsqrtf((float)(end - beg + 1));

            const float* selfp = g_bufB + (size_t)node * 64;
            ulonglong2 s0 = *(const ulonglong2*)(selfp + c * 4);
            ulonglong2 s1 = *(const ulonglong2*)(selfp + 32 + c * 4);
            ull a0 = s0.x, a1 = s0.y, a2 = s1.x, a3 = s1.y;

            int idx = beg + c;
            int ed = (idx < end) ? g_edge[idx] : NN;
            for (int j0 = beg; j0 < end; j0 += 8) {
                int nidx = j0 + 8 + c;
                int edn = (nidx < end) ? g_edge[nidx] : NN;
                #pragma unroll
                for (int k = 0; k < 8; k++) {
                    int s = __shfl_sync(gmask, ed, k, 8);
                    const float* hp = g_bufB + (size_t)s * 64;
                    ulonglong2 h0 = *(const ulonglong2*)(hp + c * 4);
                    ulonglong2 h1 = *(const ulonglong2*)(hp + 32 + c * 4);
                    ADD2(a0, h0.x); ADD2(a1, h0.y);
                    ADD2(a2, h1.x); ADD2(a3, h1.y);
                }
                ed = edn;
            }
            ull pdv; DUPF(pdv, dv);
            MUL2(a0, a0, pdv); MUL2(a1, a1, pdv);
            MUL2(a2, a2, pdv); MUL2(a3, a3, pdv);
            *(ulonglong2*)&sX[r * 68 + c * 4]      = make_ulonglong2(a0, a1);
            *(ulonglong2*)&sX[r * 68 + 32 + c * 4] = make_ulonglong2(a2, a3);

            if (c == 0) g_cnt[node] = 0;    // state re-zero for next replay
            const float4* src = (node < NU) ? (const float4*)&ue[(size_t)node * 64]
                                            : (const float4*)&ie[(size_t)(node - NU) * 64];
            size_t drow = (node < NU) ? (size_t)(NU + node)
                                      : (size_t)(2 * NU + NI + (node - NU));
            float4* dst = (float4*)&out[drow * 64];
            dst[2 * c]     = src[2 * c];
            dst[2 * c + 1] = src[2 * c + 1];
        }
        __syncthreads();

        ull acc[4];
        {
            float un1 = (node < NN) ? g_u1[node] : 0.f;
            float un2 = (node < NN) ? g_u2[node] : 0.f;
            #pragma unroll
            for (int i = 0; i < 4; i++) {
                float lo = b3[cb + 2 * i]     + un2 * g_bv2[cb + 2 * i]     + un1 * g_bv1[cb + 2 * i];
                float hi = b3[cb + 2 * i + 1] + un2 * g_bv2[cb + 2 * i + 1] + un1 * g_bv1[cb + 2 * i + 1];
                asm("mov.b64 %0, {%1, %2};" : "=l"(acc[i]) : "f"(lo), "f"(hi));
            }
        }
        #pragma unroll
        for (int k = 0; k < 64; k++) {
            float xv = sX[r * 68 + k];
            ull xvv; DUPF(xvv, xv);
            const ulonglong2* wp = (const ulonglong2*)&sW[k * 64 + cb];
            ulonglong2 wa = wp[0], wb2 = wp[1];
            FMA2(acc[0], xvv, wa.x);
            FMA2(acc[1], xvv, wa.y);
            FMA2(acc[2], xvv, wb2.x);
            FMA2(acc[3], xvv, wb2.y);
        }
        if (node < NN) {
            int orow = (node < NU) ? node : node + NU;
            ulonglong2* o = (ulonglong2*)&out[(size_t)orow * 64 + cb];
            o[0] = make_ulonglong2(acc[0], acc[1]);
            o[1] = make_ulonglong2(acc[2], acc[3]);
        }
    }
}

// ---------------------------------------------------------------------------
extern "C" void kernel_launch(void* const* d_in, const int* in_sizes, int n_in,
                              void* d_out, int out_size) {
    const int*   ei = (const int*)d_in[0];
    const float* ue = (const float*)d_in[1];
    const float* ie = (const float*)d_in[2];
    const float* Ws = (const float*)d_in[3];
    const float* bs = (const float*)d_in[4];
    float* out = (float*)d_out;

    int dev = 0;
    cudaGetDevice(&dev);
    int nsm = 148;
    cudaDeviceGetAttribute(&nsm, cudaDevAttrMultiProcessorCount, dev);
    int bpm = 1;
    cudaOccupancyMaxActiveBlocksPerMultiprocessor(&bpm, k_all, 256, 0);
    int nblk = nsm * bpm;
    if (nblk > 2048) nblk = 2048;

    k_all<<<nblk, 256>>>(nblk, ei, ue, ie, Ws, bs, out);
}

// round 15
// speedup vs baseline: 1.3989x; 1.3989x over previous
#include <cuda_runtime.h>

#define NU 100000
#define NI 50000
#define NN 150000
#define HD 64
#define NE 1200000
#define CHUNK 1024
#define NCHUNK 147   // ceil(NN / CHUNK)

typedef unsigned long long ull;

// Scratch (static device globals; zero-initialized at load).
// bufA/bufB/v1 have a zero row/slot at index NN (never written): padding target.
__device__ __align__(16) float g_bufA[(NN + 1) * HD];
__device__ __align__(16) float g_bufB[(NN + 1) * HD];
__device__ float g_u1[NN];
__device__ float g_v1[NN + 1];
__device__ float g_u2[NN];
__device__ float g_dinv[NN];
__device__ __align__(16) int g_cnt[NN];
__device__ int   g_flag[NCHUNK];
__device__ int   g_off[NN + 1];
__device__ int   g_cur[NN];
__device__ int   g_edge[NE];
__device__ float g_W123[HD * HD];
__device__ float g_T[HD * HD];
__device__ float g_bv1[HD];
__device__ float g_bv2[HD];
__device__ unsigned g_barcnt;
__device__ volatile unsigned g_bargen;

#define FMA2(acc, a, b) \
    asm("fma.rn.f32x2 %0, %1, %2, %0;" : "+l"(acc) : "l"(a), "l"(b))
#define MUL2(d, a, b) \
    asm("mul.rn.f32x2 %0, %1, %2;" : "=l"(d) : "l"(a), "l"(b))
#define ADD2(acc, b) \
    asm("add.rn.f32x2 %0, %0, %1;" : "+l"(acc) : "l"(b))
#define DUPF(d, f) \
    asm("mov.b64 %0, {%1, %1};" : "=l"(d) : "f"(f))

// Generation-counter grid barrier. Safe iff all nblk blocks co-resident
// (guaranteed by occupancy-based grid sizing at launch).
__device__ __forceinline__ void grid_bar(int nblk) {
    __threadfence();
    __syncthreads();
    if (threadIdx.x == 0) {
        unsigned gen = g_bargen;
        if (atomicAdd(&g_barcnt, 1u) == (unsigned)(nblk - 1)) {
            g_barcnt = 0u;
            __threadfence();
            g_bargen = gen + 1u;
        } else {
            while (g_bargen == gen) __nanosleep(128);
        }
        __threadfence();
    }
    __syncthreads();
}

// ---------------------------------------------------------------------------
// min-blocks 6 -> register budget 42 (the aggs' natural allocation; NO spills)
// ---------------------------------------------------------------------------
__global__ void __launch_bounds__(256, 6)
k_all(int nblk, const int* __restrict__ ei,
      const float* __restrict__ ue, const float* __restrict__ ie,
      const float* __restrict__ Wsrc, const float* __restrict__ bs,
      float* __restrict__ out)
{
    __shared__ float sW[64 * 64];    // 16 KB
    __shared__ float sX[32 * 68];    // 8.7 KB
    __shared__ int   sI[40];
    int tid  = threadIdx.x;
    int bid  = blockIdx.x;
    int nthr = nblk * 256;
    unsigned gmask = 0xFFu << (tid & 24);

    // ================= phase 1: deg (blocks 0..nblk-2) | wprod (last) =====
    if (bid == nblk - 1) {
        for (int i = tid; i < 4096; i += 256) sW[i] = Wsrc[4096 + i];   // W2
        __syncthreads();
        for (int i = tid; i < 4096; i += 256) {
            int r = i >> 6, c = i & 63;
            float s = 0.f;
            #pragma unroll
            for (int k = 0; k < 64; k++) s += sW[r * 64 + k] * Wsrc[8192 + k * 64 + c];
            g_T[i] = s;
        }
        __syncthreads();
        for (int i = tid; i < 4096; i += 256) sW[i] = Wsrc[i];          // W1
        __syncthreads();
        for (int i = tid; i < 4096; i += 256) {
            int r = i >> 6, c = i & 63;
            float s = 0.f;
            #pragma unroll
            for (int k = 0; k < 64; k++) s += sW[r * 64 + k] * g_T[k * 64 + c];
            g_W123[i] = s;
        }
        if (tid < 64) {
            float s = 0.f, s2 = 0.f;
            #pragma unroll
            for (int k = 0; k < 64; k++) {
                s  += bs[k]      * g_T[k * 64 + tid];
                s2 += bs[64 + k] * Wsrc[8192 + k * 64 + tid];
            }
            g_bv2[tid] = s;
            g_bv1[tid] = s2;
        }
    } else {
        int stride = (nblk - 1) * 256;
        for (int e = bid * 256 + tid; e < NE; e += stride)
            atomicAdd(&g_cnt[ei[NE + e]], 1);
    }
    grid_bar(nblk);

    // ================= phase 2: scan (chunked, decoupled lookback) =========
    for (int ch = bid; ch < NCHUNK; ch += nblk) {
        int base0 = ch * CHUNK + tid * 4;
        int4 cv = make_int4(0, 0, 0, 0);
        if (base0 < NN) cv = *(const int4*)&g_cnt[base0];
        int s1 = cv.x, s2v = s1 + cv.y, s3 = s2v + cv.z, s4 = s3 + cv.w;
        int lane = tid & 31, wid = tid >> 5;
        int x = s4;
        #pragma unroll
        for (int o = 1; o < 32; o <<= 1) {
            int y = __shfl_up_sync(0xffffffffu, x, o);
            if (lane >= o) x += y;
        }
        if (lane == 31) sI[wid] = x;
        if (tid == 0) sI[32] = 0;
        __syncthreads();
        if (tid < 8) {
            int v = sI[tid];
            #pragma unroll
            for (int o = 1; o < 8; o <<= 1) {
                int y = __shfl_up_sync(0xFFu, v, o);
                if (tid >= o) v += y;
            }
            sI[tid] = v;
        }
        __syncthreads();
        int total = sI[7];
        if (tid == 0) *((volatile int*)&g_flag[ch]) = total + 1;   // publish
        int thr_excl = (wid ? sI[wid - 1] : 0) + x - s4;
        for (int p = tid; p < ch; p += 256) {                      // lookback
            int v;
            do { v = *((volatile int*)&g_flag[p]); } while (v == 0);
            atomicAdd(&sI[32], v - 1);
        }
        __syncthreads();
        int gb = sI[32] + thr_excl;
        if (base0 < NN) {
            g_off[base0 + 1] = gb + s1;
            g_off[base0 + 2] = gb + s2v;
            g_off[base0 + 3] = gb + s3;
            g_off[base0 + 4] = gb + s4;
            g_cur[base0]     = gb;
            g_cur[base0 + 1] = gb + s1;
            g_cur[base0 + 2] = gb + s2v;
            g_cur[base0 + 3] = gb + s3;
            g_dinv[base0]     = rsqrtf((float)(cv.x + 1));
            g_dinv[base0 + 1] = rsqrtf((float)(cv.y + 1));
            g_dinv[base0 + 2] = rsqrtf((float)(cv.z + 1));
            g_dinv[base0 + 3] = rsqrtf((float)(cv.w + 1));
            if (base0 == 0) g_off[0] = 0;
        }
        __syncthreads();
    }
    grid_bar(nblk);

    // ================= phase 3: bucket fill ================================
    for (int e = bid * 256 + tid; e < NE; e += nthr) {
        int s = ei[e];
        int d = ei[NE + e];
        int pos = atomicAdd(&g_cur[d], 1);
        g_edge[pos] = s;
    }
    grid_bar(nblk);

    // ================= phase 4: agg1 =======================================
    // z1[d] = dinv_d^2 (sum dinv_s x0[s] + dinv_d x0[d]); u1, v1 alongside.
    for (int slot = bid * 256 + tid; slot < NN * 8; slot += nthr) {
        int node = slot >> 3;
        int c = slot & 7;
        int beg = g_off[node];
        int end = g_off[node + 1];
        float dv = rsqrtf((float)(end - beg + 1));
        ull pdv; DUPF(pdv, dv);

        const float* selfp = (node < NU) ? ue + (size_t)node * 64
                                         : ie + (size_t)(node - NU) * 64;
        ulonglong2 s0 = *(const ulonglong2*)(selfp + c * 4);
        ulonglong2 s1 = *(const ulonglong2*)(selfp + 32 + c * 4);
        ull a0, a1, a2, a3;
        MUL2(a0, s0.x, pdv); MUL2(a1, s0.y, pdv);
        MUL2(a2, s1.x, pdv); MUL2(a3, s1.y, pdv);
        float uacc = 0.0f;

        int idx = beg + c;
        int   ed = (idx < end) ? g_edge[idx] : 0;
        float wv = (idx < end) ? g_dinv[ed] : 0.0f;
        for (int j0 = beg; j0 < end; j0 += 8) {
            int nidx = j0 + 8 + c;
            int   edn = (nidx < end) ? g_edge[nidx] : 0;
            float wn  = (nidx < end) ? g_dinv[edn] : 0.0f;
            uacc += wv;
            #pragma unroll
            for (int k = 0; k < 8; k++) {
                int   s = __shfl_sync(gmask, ed, k, 8);
                float w = __shfl_sync(gmask, wv, k, 8);
                ull ww; DUPF(ww, w);
                const float* hp = (s < NU) ? ue + (size_t)s * 64
                                           : ie + (size_t)(s - NU) * 64;
                ulonglong2 h0 = *(const ulonglong2*)(hp + c * 4);
                ulonglong2 h1 = *(const ulonglong2*)(hp + 32 + c * 4);
                FMA2(a0, ww, h0.x); FMA2(a1, ww, h0.y);
                FMA2(a2, ww, h1.x); FMA2(a3, ww, h1.y);
            }
            ed = edn; wv = wn;
        }

        float dv2 = dv * dv;
        ull pdv2; DUPF(pdv2, dv2);
        MUL2(a0, a0, pdv2); MUL2(a1, a1, pdv2);
        MUL2(a2, a2, pdv2); MUL2(a3, a3, pdv2);
        *(ulonglong2*)(g_bufA + (size_t)node * 64 + c * 4)      = make_ulonglong2(a0, a1);
        *(ulonglong2*)(g_bufA + (size_t)node * 64 + 32 + c * 4) = make_ulonglong2(a2, a3);

        #pragma unroll
        for (int o = 4; o > 0; o >>= 1)
            uacc += __shfl_down_sync(gmask, uacc, o, 8);
        if (c == 0) {
            float u1 = dv * (uacc + dv);
            g_u1[node] = u1;
            g_v1[node] = dv * u1;
        }
    }
    grid_bar(nblk);

    // ================= phase 5: agg2 =======================================
    for (int slot = bid * 256 + tid; slot < NN * 8; slot += nthr) {
        int node = slot >> 3;
        int c = slot & 7;
        int beg = g_off[node];
        int end = g_off[node + 1];
        float dv = rsqrtf((float)(end - beg + 1));

        const float* selfp = g_bufA + (size_t)node * 64;
        ulonglong2 s0 = *(const ulonglong2*)(selfp + c * 4);
        ulonglong2 s1 = *(const ulonglong2*)(selfp + 32 + c * 4);
        ull a0 = s0.x, a1 = s0.y, a2 = s1.x, a3 = s1.y;
        float uacc = 0.0f;

        int idx = beg + c;
        int ed = (idx < end) ? g_edge[idx] : NN;
        for (int j0 = beg; j0 < end; j0 += 8) {
            int nidx = j0 + 8 + c;
            int edn = (nidx < end) ? g_edge[nidx] : NN;
            uacc += g_v1[ed];                     // v1[NN] == 0
            #pragma unroll
            for (int k = 0; k < 8; k++) {
                int s = __shfl_sync(gmask, ed, k, 8);
                const float* hp = g_bufA + (size_t)s * 64;
                ulonglong2 h0 = *(const ulonglong2*)(hp + c * 4);
                ulonglong2 h1 = *(const ulonglong2*)(hp + 32 + c * 4);
                ADD2(a0, h0.x); ADD2(a1, h0.y);
                ADD2(a2, h1.x); ADD2(a3, h1.y);
            }
            ed = edn;
        }

        float dv2 = dv * dv;
        ull pdv2; DUPF(pdv2, dv2);
        MUL2(a0, a0, pdv2); MUL2(a1, a1, pdv2);
        MUL2(a2, a2, pdv2); MUL2(a3, a3, pdv2);
        *(ulonglong2*)(g_bufB + (size_t)node * 64 + c * 4)      = make_ulonglong2(a0, a1);
        *(ulonglong2*)(g_bufB + (size_t)node * 64 + 32 + c * 4) = make_ulonglong2(a2, a3);

        #pragma unroll
        for (int o = 4; o > 0; o >>= 1)
            uacc += __shfl_down_sync(gmask, uacc, o, 8);
        if (c == 0) g_u2[node] = dv * (uacc + g_v1[node]);
    }
    grid_bar(nblk);

    // ================= phase 6: agg3 + GEMM + embcopy + state re-zero ======
    for (int i = tid; i < 1024; i += 256)
        ((float4*)sW)[i] = ((const float4*)g_W123)[i];
    if (bid == 0 && tid < NCHUNK) g_flag[tid] = 0;
    const float* b3 = bs + 128;
    int r = tid >> 3;
    int c = tid & 7;
    int cb = c << 3;

    for (int t = bid; t < (NN + 31) / 32; t += nblk) {
        __syncthreads();                    // sW ready / sX reuse safe
        int node = t * 32 + r;
        if (node < NN) {
            int beg = g_off[node];
            int end = g_off[node + 1];
            float dv = rsqrtf((float)(end - beg + 1));

            const float* selfp = g_bufB + (size_t)node * 64;
            ulonglong2 s0 = *(const ulonglong2*)(selfp + c * 4);
            ulonglong2 s1 = *(const ulonglong2*)(selfp + 32 + c * 4);
            ull a0 = s0.x, a1 = s0.y, a2 = s1.x, a3 = s1.y;

            int idx = beg + c;
            int ed = (idx < end) ? g_edge[idx] : NN;
            for (int j0 = beg; j0 < end; j0 += 8) {
                int nidx = j0 + 8 + c;
                int edn = (nidx < end) ? g_edge[nidx] : NN;
                #pragma unroll
                for (int k = 0; k < 8; k++) {
                    int s = __shfl_sync(gmask, ed, k, 8);
                    const float* hp = g_bufB + (size_t)s * 64;
                    ulonglong2 h0 = *(const ulonglong2*)(hp + c * 4);
                    ulonglong2 h1 = *(const ulonglong2*)(hp + 32 + c * 4);
                    ADD2(a0, h0.x); ADD2(a1, h0.y);
                    ADD2(a2, h1.x); ADD2(a3, h1.y);
                }
                ed = edn;
            }
            ull pdv; DUPF(pdv, dv);
            MUL2(a0, a0, pdv); MUL2(a1, a1, pdv);
            MUL2(a2, a2, pdv); MUL2(a3, a3, pdv);
            *(ulonglong2*)&sX[r * 68 + c * 4]      = make_ulonglong2(a0, a1);
            *(ulonglong2*)&sX[r * 68 + 32 + c * 4] = make_ulonglong2(a2, a3);

            if (c == 0) g_cnt[node] = 0;    // state re-zero for next replay
            const float4* src = (node < NU) ? (const float4*)&ue[(size_t)node * 64]
                                            : (const float4*)&ie[(size_t)(node - NU) * 64];
            size_t drow = (node < NU) ? (size_t)(NU + node)
                                      : (size_t)(2 * NU + NI + (node - NU));
            float4* dst = (float4*)&out[drow * 64];
            dst[2 * c]     = src[2 * c];
            dst[2 * c + 1] = src[2 * c + 1];
        }
        __syncthreads();

        ull acc[4];
        {
            float un1 = (node < NN) ? g_u1[node] : 0.f;
            float un2 = (node < NN) ? g_u2[node] : 0.f;
            #pragma unroll
            for (int i = 0; i < 4; i++) {
                float lo = b3[cb + 2 * i]     + un2 * g_bv2[cb + 2 * i]     + un1 * g_bv1[cb + 2 * i];
                float hi = b3[cb + 2 * i + 1] + un2 * g_bv2[cb + 2 * i + 1] + un1 * g_bv1[cb + 2 * i + 1];
                asm("mov.b64 %0, {%1, %2};" : "=l"(acc[i]) : "f"(lo), "f"(hi));
            }
        }
        #pragma unroll
        for (int k = 0; k < 64; k++) {
            float xv = sX[r * 68 + k];
            ull xvv; DUPF(xvv, xv);
            const ulonglong2* wp = (const ulonglong2*)&sW[k * 64 + cb];
            ulonglong2 wa = wp[0], wb2 = wp[1];
            FMA2(acc[0], xvv, wa.x);
            FMA2(acc[1], xvv, wa.y);
            FMA2(acc[2], xvv, wb2.x);
            FMA2(acc[3], xvv, wb2.y);
        }
        if (node < NN) {
            int orow = (node < NU) ? node : node + NU;
            ulonglong2* o = (ulonglong2*)&out[(size_t)orow * 64 + cb];
            o[0] = make_ulonglong2(acc[0], acc[1]);
            o[1] = make_ulonglong2(acc[2], acc[3]);
        }
    }
}

// ---------------------------------------------------------------------------
extern "C" void kernel_launch(void* const* d_in, const int* in_sizes, int n_in,
                              void* d_out, int out_size) {
    const int*   ei = (const int*)d_in[0];
    const float* ue = (const float*)d_in[1];
    const float* ie = (const float*)d_in[2];
    const float* Ws = (const float*)d_in[3];
    const float* bs = (const float*)d_in[4];
    float* out = (float*)d_out;

    int dev = 0;
    cudaGetDevice(&dev);
    int nsm = 148;
    cudaDeviceGetAttribute(&nsm, cudaDevAttrMultiProcessorCount, dev);
    int bpm = 1;
    cudaOccupancyMaxActiveBlocksPerMultiprocessor(&bpm, k_all, 256, 0);
    if (bpm > 6) bpm = 6;          // match __launch_bounds__(256, 6) budget
    int nblk = nsm * bpm;

    k_all<<<nblk, 256>>>(nblk, ei, ue, ie, Ws, bs, out);
}

// round 16
// speedup vs baseline: 1.7912x; 1.2804x over previous
#include <cuda_runtime.h>

#define NU 100000
#define NI 50000
#define NN 150000
#define HD 64
#define NE 1200000
#define SCAN_B 1024
#define NBLK ((NN + SCAN_B - 1) / SCAN_B)   // 147

typedef unsigned long long ull;

// Scratch (static device globals; zero-initialized at load).
// bufA/bufB/v1 have a zero row/slot at index NN (never written): padding target.
__device__ __align__(16) float g_bufA[(NN + 1) * HD];
__device__ __align__(16) float g_bufB[(NN + 1) * HD];
__device__ float g_u1[NN];
__device__ float g_v1[NN + 1];
__device__ float g_u2[NN];
__device__ float g_dinv[NN];
__device__ int   g_cnt[NN];
__device__ int   g_flag[NBLK];
__device__ int   g_off[NN + 1];
__device__ int   g_cur[NN];
__device__ int   g_edge[NE];
__device__ float g_W123[HD * HD];
__device__ float g_bv1[HD];
__device__ float g_bv2[HD];

#define FMA2(acc, a, b) \
    asm("fma.rn.f32x2 %0, %1, %2, %0;" : "+l"(acc) : "l"(a), "l"(b))
#define MUL2(d, a, b) \
    asm("mul.rn.f32x2 %0, %1, %2;" : "=l"(d) : "l"(a), "l"(b))
#define ADD2(acc, b) \
    asm("add.rn.f32x2 %0, %0, %1;" : "+l"(acc) : "l"(b))
#define DUPF(d, f) \
    asm("mov.b64 %0, {%1, %1};" : "=l"(d) : "f"(f))

// ---------------------------------------------------------------------------
__global__ void k_deg(const int* __restrict__ ei) {
    int e = blockIdx.x * blockDim.x + threadIdx.x;
    if (e < NE) atomicAdd(&g_cnt[ei[NE + e]], 1);
}

// ---------------------------------------------------------------------------
// Fused: blocks 0..NBLK-1 = single-pass scan of g_cnt + dinv;
// block NBLK = weight/bias products.
// ---------------------------------------------------------------------------
__global__ void __launch_bounds__(1024)
k_scan_wprod(const float* __restrict__ Wsrc, const float* __restrict__ bs) {
    __shared__ float smem[3 * 4096 + 64];
    int tid = threadIdx.x;

    if (blockIdx.x < NBLK) {
        int* ws    = (int*)smem;
        int* basep = (int*)smem + 40;
        if (tid == 0) *basep = 0;
        int i = blockIdx.x * SCAN_B + tid;
        int lane = tid & 31, wid = tid >> 5;
        int cnt = (i < NN) ? g_cnt[i] : 0;
        if (i < NN) g_dinv[i] = rsqrtf((float)(cnt + 1));
        int x = cnt;
        #pragma unroll
        for (int o = 1; o < 32; o <<= 1) {
            int y = __shfl_up_sync(0xffffffffu, x, o);
            if (lane >= o) x += y;
        }
        if (lane == 31) ws[wid] = x;
        __syncthreads();
        if (wid == 0) {
            int s = ws[lane];
            #pragma unroll
            for (int o = 1; o < 32; o <<= 1) {
                int y = __shfl_up_sync(0xffffffffu, s, o);
                if (lane >= o) s += y;
            }
            ws[lane] = s;
        }
        __syncthreads();
        int incl = x + (wid > 0 ? ws[wid - 1] : 0);

        if (tid == SCAN_B - 1)
            *((volatile int*)&g_flag[blockIdx.x]) = incl + 1;

        if (tid < blockIdx.x) {
            int v;
            do { v = *((volatile int*)&g_flag[tid]); } while (v == 0);
            atomicAdd(basep, v - 1);
        }
        __syncthreads();

        if (i < NN) {
            int g = incl + *basep;
            g_off[i + 1] = g;
            g_cur[i] = g - cnt;
            if (i == 0) g_off[0] = 0;
        }
    } else {
        float* A = smem;
        float* B = smem + 4096;
        float* T = smem + 8192;
        ((float4*)A)[tid] = ((const float4*)(Wsrc + 4096))[tid];   // W2
        ((float4*)B)[tid] = ((const float4*)(Wsrc + 8192))[tid];   // W3
        __syncthreads();
        #pragma unroll
        for (int i = 0; i < 4; i++) {            // T = W2@W3
            int idx = tid * 4 + i, r = idx >> 6, c = idx & 63;
            float s = 0.f;
            #pragma unroll
            for (int k = 0; k < 64; k++) s += A[r * 64 + k] * B[k * 64 + c];
            T[idx] = s;
        }
        __syncthreads();
        ((float4*)A)[tid] = ((const float4*)Wsrc)[tid];            // W1
        __syncthreads();
        #pragma unroll
        for (int i = 0; i < 4; i++) {            // W123 = W1@T
            int idx = tid * 4 + i, r = idx >> 6, c = idx & 63;
            float s = 0.f;
            #pragma unroll
            for (int k = 0; k < 64; k++) s += A[r * 64 + k] * T[k * 64 + c];
            g_W123[idx] = s;
        }
        if (tid < 64) {                          // bv2 = b1@T
            float s = 0.f;
            #pragma unroll
            for (int k = 0; k < 64; k++) s += bs[k] * T[k * 64 + tid];
            g_bv2[tid] = s;
        } else if (tid < 128) {                  // bv1 = b2@W3
            int c = tid - 64;
            float s = 0.f;
            #pragma unroll
            for (int k = 0; k < 64; k++) s += bs[64 + k] * B[k * 64 + c];
            g_bv1[c] = s;
        }
    }
}

// ---------------------------------------------------------------------------
__global__ void k_fill(const int* __restrict__ ei) {
    int e = blockIdx.x * blockDim.x + threadIdx.x;
    if (e >= NE) return;
    int s = ei[e];
    int d = ei[NE + e];
    int pos = atomicAdd(&g_cur[d], 1);
    g_edge[pos] = s;
}

// ---------------------------------------------------------------------------
// agg1 (16 lanes/node): z1[d] = dinv_d^2 (sum dinv_s x0[s] + dinv_d x0[d])
// Lane c owns cols [4c,4c+4). Edge batch of 8 loaded via (c&7); width-16
// shuffle broadcast. u1/v1 alongside (low 8 lanes accumulate).
// ---------------------------------------------------------------------------
__global__ void __launch_bounds__(256, 7)
k_agg1(const float* __restrict__ ue, const float* __restrict__ ie,
       float* __restrict__ y) {
    int t = blockIdx.x * blockDim.x + threadIdx.x;
    int node = t >> 4;
    int c = t & 15;
    if (node >= NN) return;
    unsigned gmask = 0xFFFFu << (threadIdx.x & 16);

    int beg = g_off[node];
    int end = g_off[node + 1];
    float dv = rsqrtf((float)(end - beg + 1));
    ull pdv; DUPF(pdv, dv);

    const float* selfp = (node < NU) ? ue + (size_t)node * 64
                                     : ie + (size_t)(node - NU) * 64;
    ulonglong2 s0 = *(const ulonglong2*)(selfp + c * 4);
    ull a0, a1;
    MUL2(a0, s0.x, pdv); MUL2(a1, s0.y, pdv);
    float uacc = 0.0f;

    int idx = beg + (c & 7);
    int   ed = (idx < end) ? g_edge[idx] : 0;
    float wv = (idx < end) ? g_dinv[ed] : 0.0f;
    for (int j0 = beg; j0 < end; j0 += 8) {
        int nidx = j0 + 8 + (c & 7);
        int   edn = (nidx < end) ? g_edge[nidx] : 0;
        float wn  = (nidx < end) ? g_dinv[edn] : 0.0f;
        if (c < 8) uacc += wv;
        #pragma unroll
        for (int k = 0; k < 8; k++) {
            int   s = __shfl_sync(gmask, ed, k, 16);
            float w = __shfl_sync(gmask, wv, k, 16);
            ull ww; DUPF(ww, w);
            const float* hp = (s < NU) ? ue + (size_t)s * 64
                                       : ie + (size_t)(s - NU) * 64;
            ulonglong2 h = *(const ulonglong2*)(hp + c * 4);
            FMA2(a0, ww, h.x); FMA2(a1, ww, h.y);
        }
        ed = edn; wv = wn;
    }

    float dv2 = dv * dv;
    ull pdv2; DUPF(pdv2, dv2);
    MUL2(a0, a0, pdv2); MUL2(a1, a1, pdv2);
    *(ulonglong2*)(y + (size_t)node * 64 + c * 4) = make_ulonglong2(a0, a1);

    #pragma unroll
    for (int o = 8; o > 0; o >>= 1)
        uacc += __shfl_down_sync(gmask, uacc, o, 16);
    if (c == 0) {
        float u1 = dv * (uacc + dv);
        g_u1[node] = u1;
        g_v1[node] = dv * u1;
    }
}

// ---------------------------------------------------------------------------
// agg2 (16 lanes/node): z2[d] = dinv_d^2 (sum z1[s] + z1[d]); u2 alongside.
// Padding edges -> zero row NN (exact no-op).
// ---------------------------------------------------------------------------
__global__ void __launch_bounds__(256, 7)
k_agg2(const float* __restrict__ x, float* __restrict__ y) {
    int t = blockIdx.x * blockDim.x + threadIdx.x;
    int node = t >> 4;
    int c = t & 15;
    if (node >= NN) return;
    unsigned gmask = 0xFFFFu << (threadIdx.x & 16);

    int beg = g_off[node];
    int end = g_off[node + 1];
    float dv = rsqrtf((float)(end - beg + 1));

    const float* selfp = x + (size_t)node * 64;
    ulonglong2 s0 = *(const ulonglong2*)(selfp + c * 4);
    ull a0 = s0.x, a1 = s0.y;
    float uacc = 0.0f;

    int idx = beg + (c & 7);
    int ed = (idx < end) ? g_edge[idx] : NN;
    for (int j0 = beg; j0 < end; j0 += 8) {
        int nidx = j0 + 8 + (c & 7);
        int edn = (nidx < end) ? g_edge[nidx] : NN;
        if (c < 8) uacc += g_v1[ed];          // v1[NN] == 0
        #pragma unroll
        for (int k = 0; k < 8; k++) {
            int s = __shfl_sync(gmask, ed, k, 16);
            const float* hp = x + (size_t)s * 64;
            ulonglong2 h = *(const ulonglong2*)(hp + c * 4);
            ADD2(a0, h.x); ADD2(a1, h.y);
        }
        ed = edn;
    }

    float dv2 = dv * dv;
    ull pdv2; DUPF(pdv2, dv2);
    MUL2(a0, a0, pdv2); MUL2(a1, a1, pdv2);
    *(ulonglong2*)(y + (size_t)node * 64 + c * 4) = make_ulonglong2(a0, a1);

    #pragma unroll
    for (int o = 8; o > 0; o >>= 1)
        uacc += __shfl_down_sync(gmask, uacc, o, 16);
    if (c == 0) g_u2[node] = dv * (uacc + g_v1[node]);
}

// ---------------------------------------------------------------------------
// Fused agg3 + final GEMM (512 threads = 32 nodes x 16 lanes):
//   y3[d] = dinv_d (sum z2[s] + z2[d]) staged in smem,
//   out[remap] = y3@W123 + u2*bv2 + u1*bv1 + b3.
// Also copies raw embeddings to out segments 1/3 and re-zeroes g_cnt/g_flag.
// ---------------------------------------------------------------------------
__global__ void __launch_bounds__(512)
k_agg_gemm(const float* __restrict__ x, const float* __restrict__ b3,
           const float* __restrict__ ue, const float* __restrict__ ie,
           float* __restrict__ out) {
    __shared__ float sW[64 * 64];
    __shared__ float sX[32 * 68];
    int tid  = threadIdx.x;
    int r = tid >> 4;          // 0..31
    int c = tid & 15;          // 0..15
    int node = blockIdx.x * 32 + r;
    unsigned gmask = 0xFFFFu << (tid & 16);

    #pragma unroll
    for (int i = 0; i < 2; i++)
        ((float4*)sW)[tid + i * 512] = ((const float4*)g_W123)[tid + i * 512];

    if (blockIdx.x == 0 && tid < NBLK) g_flag[tid] = 0;

    if (node < NN) {
        int beg = g_off[node];
        int end = g_off[node + 1];
        float dv = rsqrtf((float)(end - beg + 1));

        const float* selfp = x + (size_t)node * 64;
        ulonglong2 s0 = *(const ulonglong2*)(selfp + c * 4);
        ull a0 = s0.x, a1 = s0.y;

        int idx = beg + (c & 7);
        int ed = (idx < end) ? g_edge[idx] : NN;
        for (int j0 = beg; j0 < end; j0 += 8) {
            int nidx = j0 + 8 + (c & 7);
            int edn = (nidx < end) ? g_edge[nidx] : NN;
            #pragma unroll
            for (int k = 0; k < 8; k++) {
                int s = __shfl_sync(gmask, ed, k, 16);
                const float* hp = x + (size_t)s * 64;
                ulonglong2 h = *(const ulonglong2*)(hp + c * 4);
                ADD2(a0, h.x); ADD2(a1, h.y);
            }
            ed = edn;
        }
        ull pdv; DUPF(pdv, dv);
        MUL2(a0, a0, pdv); MUL2(a1, a1, pdv);
        *(ulonglong2*)&sX[r * 68 + c * 4] = make_ulonglong2(a0, a1);

        // embedding passthrough + state re-zero
        if (c == 0) g_cnt[node] = 0;
        const float4* src = (node < NU) ? (const float4*)&ue[(size_t)node * 64]
                                        : (const float4*)&ie[(size_t)(node - NU) * 64];
        size_t drow = (node < NU) ? (size_t)(NU + node)
                                  : (size_t)(2 * NU + NI + (node - NU));
        ((float4*)&out[drow * 64])[c] = src[c];
    }
    __syncthreads();

    // ---- GEMM phase: thread -> (row r, cols 4c .. 4c+3) ----
    int cb = c << 2;
    ull acc[2];
    {
        float un1 = (node < NN) ? g_u1[node] : 0.f;
        float un2 = (node < NN) ? g_u2[node] : 0.f;
        #pragma unroll
        for (int i = 0; i < 2; i++) {
            float lo = b3[cb + 2 * i]     + un2 * g_bv2[cb + 2 * i]     + un1 * g_bv1[cb + 2 * i];
            float hi = b3[cb + 2 * i + 1] + un2 * g_bv2[cb + 2 * i + 1] + un1 * g_bv1[cb + 2 * i + 1];
            asm("mov.b64 %0, {%1, %2};" : "=l"(acc[i]) : "f"(lo), "f"(hi));
        }
    }
    #pragma unroll
    for (int k = 0; k < 64; k++) {
        float xv = sX[r * 68 + k];
        ull xvv; DUPF(xvv, xv);
        const ulonglong2* wp = (const ulonglong2*)&sW[k * 64 + cb];
        ulonglong2 wa = wp[0];
        FMA2(acc[0], xvv, wa.x);
        FMA2(acc[1], xvv, wa.y);
    }
    if (node < NN) {
        int orow = (node < NU) ? node : node + NU;
        *(ulonglong2*)&out[(size_t)orow * 64 + cb] = make_ulonglong2(acc[0], acc[1]);
    }
}

// ---------------------------------------------------------------------------
extern "C" void kernel_launch(void* const* d_in, const int* in_sizes, int n_in,
                              void* d_out, int out_size) {
    const int*   ei = (const int*)d_in[0];
    const float* ue = (const float*)d_in[1];
    const float* ie = (const float*)d_in[2];
    const float* Ws = (const float*)d_in[3];
    const float* bs = (const float*)d_in[4];
    float* out = (float*)d_out;

    float *bufA, *bufB;
    cudaGetSymbolAddress((void**)&bufA, g_bufA);
    cudaGetSymbolAddress((void**)&bufB, g_bufB);

    const int TB = 256;
    const int AGG_GRID = (NN * 16 + TB - 1) / TB;   // 9375
    k_deg       <<<(NE + TB - 1) / TB, TB>>>(ei);              // 1
    k_scan_wprod<<<NBLK + 1, SCAN_B>>>(Ws, bs);                // 2
    k_fill      <<<(NE + TB - 1) / TB, TB>>>(ei);              // 3
    k_agg1      <<<AGG_GRID, TB>>>(ue, ie, bufA);              // 4 <- profiled
    k_agg2      <<<AGG_GRID, TB>>>(bufA, bufB);                // 5
    k_agg_gemm  <<<(NN + 31) / 32, 512>>>(bufB, bs + 2 * 64, ue, ie, out);  // 6
}